// round 6
// baseline (speedup 1.0000x reference)
#include <cuda_runtime.h>
#include <cuda_fp16.h>
#include <cstdint>

#define NB 8
#define NT 1024
#define NC 512
#define NH 4
#define BT (NB*NT)          // 8192
#define NF 2048             // NH*NC

// ---------------- scratch (device globals) ----------------
__device__ __half g_h[BT * NC];                     // [bt][c]
__device__ __half g_qkT[(long long)4096 * BT];      // rows 0..2047 Q(h*512+c), 2048..4095 K ; [row][bt]
__device__ __half g_v2[(long long)BT * NF];         // [bt][h*512+d]
__device__ float  g_attn[32 * NC * NC];             // [b*4+h][c][d]  (fp32 logits)
__device__ __half g_attnh[32 * NC * NC];            // softmaxed, fp16
__device__ __half g_av2[(long long)BT * NF];        // [bt][h*512+c]
__device__ __half g_wqkT[6144 * NC];                // [row][c] row: sec*2048 + h*512 + c (sec 2 = V)
__device__ __half g_woutT[NC * NF];                 // [c][f]
__device__ float  g_mean[NB * 32];
__device__ float  g_rstd[NB * 32];

__device__ __forceinline__ uint32_t smem_u32(const void* p) {
    uint32_t a;
    asm("{ .reg .u64 t; cvta.to.shared.u64 t, %1; cvt.u32.u64 %0, t; }" : "=r"(a) : "l"(p));
    return a;
}
#define SWZ(o) ((o) ^ (((o) >> 3) & 0x70))

#define CPASYNC16(dst, src) \
    asm volatile("cp.async.cg.shared.global [%0], [%1], 16;" :: "r"(dst), "l"(src))
#define CP_COMMIT() asm volatile("cp.async.commit_group;" ::: "memory")
#define CP_WAIT1()  asm volatile("cp.async.wait_group 1;" ::: "memory")

#define LDSM4(r0, r1, r2, r3, addr) \
    asm volatile("ldmatrix.sync.aligned.m8n8.x4.shared.b16 {%0,%1,%2,%3}, [%4];" \
        : "=r"(r0), "=r"(r1), "=r"(r2), "=r"(r3) : "r"(addr))

#define HMMA16(d, a0, a1, a2, a3, b0, b1) \
    asm volatile("mma.sync.aligned.m16n8k16.row.col.f32.f16.f16.f32 " \
        "{%0,%1,%2,%3}, {%4,%5,%6,%7}, {%8,%9}, {%0,%1,%2,%3};" \
        : "+f"((d)[0]), "+f"((d)[1]), "+f"((d)[2]), "+f"((d)[3]) \
        : "r"(a0), "r"(a1), "r"(a2), "r"(a3), "r"(b0), "r"(b1))

// ---------------- GroupNorm ----------------
__global__ void gn_stats(const float* __restrict__ x) {
    int bg = blockIdx.x;
    int b = bg >> 5, g = bg & 31;
    const float* base = x + (size_t)b * (NT * NC) + g * 16;
    float s = 0.f, ss = 0.f;
    for (int idx = threadIdx.x; idx < NT * 16; idx += 256) {
        float v = base[(idx >> 4) * NC + (idx & 15)];
        s += v; ss += v * v;
    }
    for (int o = 16; o; o >>= 1) {
        s  += __shfl_xor_sync(0xffffffffu, s,  o);
        ss += __shfl_xor_sync(0xffffffffu, ss, o);
    }
    __shared__ float sa[8], sb[8];
    int wid = threadIdx.x >> 5;
    if ((threadIdx.x & 31) == 0) { sa[wid] = s; sb[wid] = ss; }
    __syncthreads();
    if (threadIdx.x == 0) {
        float S = 0.f, SS = 0.f;
        #pragma unroll
        for (int i = 0; i < 8; i++) { S += sa[i]; SS += sb[i]; }
        float inv = 1.0f / (NT * 16);
        float mean = S * inv;
        float var  = SS * inv - mean * mean;
        g_mean[bg] = mean;
        g_rstd[bg] = rsqrtf(var + 1e-5f);
    }
}

__global__ void gn_apply(const float* __restrict__ x,
                         const float* __restrict__ scale,
                         const float* __restrict__ bias) {
    int idx = blockIdx.x * 256 + threadIdx.x;
    if (idx >= BT * NC) return;
    int c = idx & (NC - 1);
    int b = idx >> 19;
    int bg = b * 32 + (c >> 4);
    float v = (x[idx] - g_mean[bg]) * g_rstd[bg] * scale[c] + bias[c];
    g_h[idx] = __float2half(v);
}

// ---------------- weight transposes ----------------
__global__ void tr_wqkv(const float* __restrict__ w, __half* __restrict__ wT) {
    __shared__ float t[32][33];
    int blk = blockIdx.x;             // 0..191
    int sec = blk >> 6;
    int within = blk & 63;
    int h = within >> 4, ct = within & 15;
    int c0 = ct * 32;
    int fbase = h * 1536 + sec;
    int r0 = sec * 2048 + h * 512 + c0;
    int tx = threadIdx.x & 31, ty = threadIdx.x >> 5;
    for (int k0 = 0; k0 < 512; k0 += 32) {
        #pragma unroll
        for (int j = 0; j < 4; j++) {
            int k = ty + j * 8;
            t[k][tx] = w[(long long)(k0 + k) * 6144 + fbase + 3 * (c0 + tx)];
        }
        __syncthreads();
        #pragma unroll
        for (int j = 0; j < 4; j++) {
            int cc = ty + j * 8;
            wT[(long long)(r0 + cc) * 512 + k0 + tx] = __float2half(t[tx][cc]);
        }
        __syncthreads();
    }
}

__global__ void tr_wout(const float* __restrict__ w, __half* __restrict__ wT) {
    __shared__ float t[32][33];
    int f0 = blockIdx.x * 32, c0 = blockIdx.y * 32;
    int tx = threadIdx.x & 31, ty = threadIdx.x >> 5;
    #pragma unroll
    for (int j = 0; j < 4; j++)
        t[ty + j * 8][tx] = w[(long long)(f0 + ty + j * 8) * 512 + c0 + tx];
    __syncthreads();
    #pragma unroll
    for (int j = 0; j < 4; j++)
        wT[(long long)(c0 + ty + j * 8) * 2048 + f0 + tx] = __float2half(t[tx][ty + j * 8]);
}

// ---------------- softmax: fp32 in, fp16 out ----------------
__global__ void softmax512(const float* __restrict__ a, __half* __restrict__ o) {
    const float* row = a + (size_t)blockIdx.x * NC;
    __half* orow = o + (size_t)blockIdx.x * NC;
    int tid = threadIdx.x;
    float v0 = row[tid], v1 = row[tid + 256];
    float m = fmaxf(v0, v1);
    __shared__ float red[8];
    for (int off = 16; off; off >>= 1) m = fmaxf(m, __shfl_xor_sync(0xffffffffu, m, off));
    if ((tid & 31) == 0) red[tid >> 5] = m;
    __syncthreads();
    m = red[0];
    #pragma unroll
    for (int i = 1; i < 8; i++) m = fmaxf(m, red[i]);
    __syncthreads();
    float e0 = __expf(v0 - m), e1 = __expf(v1 - m);
    float s = e0 + e1;
    for (int off = 16; off; off >>= 1) s += __shfl_xor_sync(0xffffffffu, s, off);
    if ((tid & 31) == 0) red[tid >> 5] = s;
    __syncthreads();
    s = 0.f;
    #pragma unroll
    for (int i = 0; i < 8; i++) s += red[i];
    float inv = 1.0f / s;
    orow[tid] = __float2half(e0 * inv);
    orow[tid + 256] = __float2half(e1 * inv);
}

// ---------------- fp16 mma.sync GEMM: CTA 256x128, warp 64x64, BK=64 ----------
// C[m,n] = alpha*sum_k A[m,k]B[n,k] (+bias_m +bias_n +resid). A,B k-contiguous fp16.
// 8 warps arranged 4(M) x 2(N). smem stage = A(256x64h=32KB)+B(128x64h=16KB)=48KB, 3 stages.
// bmode: 1 = bias_m index remapped sec/h/c -> qkv ; 2 = bias_n remapped (V) ; 0 = direct.

#define STAGEB 49152
#define GSMEM (3 * STAGEB)

__device__ __forceinline__ int qkv_map_m(int r) {
    int sec = r >> 11, rem = r & 2047;
    return (rem >> 9) * 1536 + 3 * (rem & 511) + sec;
}
__device__ __forceinline__ int qkv_map_v(int n) {
    return (n >> 9) * 1536 + 3 * (n & 511) + 2;
}

__global__ void __launch_bounds__(256, 1)
hgemm(const __half* __restrict__ A, const __half* __restrict__ B, void* __restrict__ Cv,
      int K, long long Asm, long long Bsn, long long Csm,
      int zInner, long long Abi, long long Abo, long long Bbi, long long Bbo,
      long long Cbi, long long Cbo, float alpha,
      const float* __restrict__ bias_m, const float* __restrict__ bias_n,
      const float* __restrict__ resid, int c16, int bmode) {
    extern __shared__ char smem[];
    uint32_t sbase = smem_u32(smem);
    int tid = threadIdx.x, lane = tid & 31, wid = tid >> 5;
    int g = lane >> 2, qid = lane & 3;
    int wm = (wid & 3) * 64, wn = (wid >> 2) * 64;

    int z = blockIdx.z;
    int zi = z % zInner, zo = z / zInner;
    A += zi * Abi + zo * Abo;
    B += zi * Bbi + zo * Bbo;
    long long cbase = zi * Cbi + zo * Cbo;
    int m0 = blockIdx.y * 256;
    int n0 = blockIdx.x * 128;
    A += (long long)m0 * Asm;
    B += (long long)n0 * Bsn;

    // cp.async mapping: A 32KB = 2048 chunks (8/thread), B 16KB = 1024 chunks (4/thread)
    int row0 = tid >> 3, q0 = tid & 7;
    const __half* srcA = A + (long long)row0 * Asm + q0 * 8;
    const __half* srcB = B + (long long)row0 * Bsn + q0 * 8;
    uint32_t dstA = sbase + SWZ((uint32_t)(row0 * 128 + q0 * 16));
    uint32_t dstB = dstA + 32768;

    float acc[4][8][4];
    #pragma unroll
    for (int i = 0; i < 4; i++)
        #pragma unroll
        for (int j = 0; j < 8; j++)
            #pragma unroll
            for (int qq = 0; qq < 4; qq++) acc[i][j][qq] = 0.f;

    int KB = K >> 6;

    #pragma unroll
    for (int s = 0; s < 2; s++) {
        uint32_t so = s * STAGEB;
        #pragma unroll
        for (int t = 0; t < 8; t++)
            CPASYNC16(dstA + so + t * 4096, srcA + s * 64 + (long long)(32 * t) * Asm);
        #pragma unroll
        for (int t = 0; t < 4; t++)
            CPASYNC16(dstB + so + t * 4096, srcB + s * 64 + (long long)(32 * t) * Bsn);
        CP_COMMIT();
    }

    uint32_t baseA = (uint32_t)((wm + (lane & 15)) * 128 + (lane >> 4) * 16);
    uint32_t baseB = (uint32_t)((wn + (lane & 7) + ((lane >> 4) & 1) * 8) * 128 + ((lane >> 3) & 1) * 16);

    int st = 0;
    for (int kb = 0; kb < KB; kb++) {
        CP_WAIT1();
        __syncthreads();
        if (kb + 2 < KB) {
            int s2 = st + 2; if (s2 >= 3) s2 -= 3;
            uint32_t so = (uint32_t)s2 * STAGEB;
            #pragma unroll
            for (int t = 0; t < 8; t++)
                CPASYNC16(dstA + so + t * 4096, srcA + (kb + 2) * 64 + (long long)(32 * t) * Asm);
            #pragma unroll
            for (int t = 0; t < 4; t++)
                CPASYNC16(dstB + so + t * 4096, srcB + (kb + 2) * 64 + (long long)(32 * t) * Bsn);
        }
        CP_COMMIT();

        uint32_t sA = sbase + st * STAGEB;
        uint32_t sB = sA + 32768;

        #pragma unroll
        for (int ks = 0; ks < 4; ks++) {
            uint32_t a[4][4], bf[4][4];
            #pragma unroll
            for (int mt = 0; mt < 4; mt++)
                LDSM4(a[mt][0], a[mt][1], a[mt][2], a[mt][3],
                      sA + SWZ(baseA + mt * 2048 + ks * 32));
            #pragma unroll
            for (int ntp = 0; ntp < 4; ntp++)
                LDSM4(bf[ntp][0], bf[ntp][1], bf[ntp][2], bf[ntp][3],
                      sB + SWZ(baseB + ntp * 2048 + ks * 32));
            #pragma unroll
            for (int mt = 0; mt < 4; mt++)
                #pragma unroll
                for (int nt = 0; nt < 8; nt++) {
                    uint32_t b0 = bf[nt >> 1][(nt & 1) * 2];
                    uint32_t b1 = bf[nt >> 1][(nt & 1) * 2 + 1];
                    HMMA16(acc[mt][nt], a[mt][0], a[mt][1], a[mt][2], a[mt][3], b0, b1);
                }
        }
        st++; if (st == 3) st = 0;
    }

    // ---------------- epilogue ----------------
    #pragma unroll
    for (int mt = 0; mt < 4; mt++) {
        int r = m0 + wm + 16 * mt + g;
        float bm0 = 0.f, bm1 = 0.f;
        if (bias_m) {
            if (bmode == 1) { bm0 = bias_m[qkv_map_m(r)]; bm1 = bias_m[qkv_map_m(r + 8)]; }
            else            { bm0 = bias_m[r]; bm1 = bias_m[r + 8]; }
        }
        #pragma unroll
        for (int nt = 0; nt < 8; nt++) {
            float* c = acc[mt][nt];
            int n = n0 + wn + 8 * nt + qid * 2;
            float bn0 = 0.f, bn1 = 0.f;
            if (bias_n) {
                if (bmode == 2) { bn0 = bias_n[qkv_map_v(n)]; bn1 = bias_n[qkv_map_v(n + 1)]; }
                else            { bn0 = bias_n[n]; bn1 = bias_n[n + 1]; }
            }
            float v00 = c[0] * alpha + bm0 + bn0;
            float v01 = c[1] * alpha + bm0 + bn1;
            float v10 = c[2] * alpha + bm1 + bn0;
            float v11 = c[3] * alpha + bm1 + bn1;
            long long o0 = cbase + (long long)r * Csm + n;
            long long o1 = cbase + (long long)(r + 8) * Csm + n;
            if (c16) {
                *(__half2*)((__half*)Cv + o0) = __floats2half2_rn(v00, v01);
                *(__half2*)((__half*)Cv + o1) = __floats2half2_rn(v10, v11);
            } else {
                float* C = (float*)Cv;
                if (resid) {
                    v00 += resid[o0]; v01 += resid[o0 + 1];
                    v10 += resid[o1]; v11 += resid[o1 + 1];
                }
                *(float2*)(C + o0) = make_float2(v00, v01);
                *(float2*)(C + o1) = make_float2(v10, v11);
            }
        }
    }
}

extern "C" void kernel_launch(void* const* d_in, const int* in_sizes, int n_in,
                              void* d_out, int out_size) {
    const float* x        = (const float*)d_in[0];
    const float* gn_scale = (const float*)d_in[1];
    const float* gn_bias  = (const float*)d_in[2];
    const float* w_qkv    = (const float*)d_in[3];
    const float* b_qkv    = (const float*)d_in[4];
    const float* w_out    = (const float*)d_in[5];
    const float* b_out    = (const float*)d_in[6];
    float* out = (float*)d_out;

    __half *h, *qkT, *v2, *attnh, *av2, *wqkT, *woutT;
    float *attn;
    cudaGetSymbolAddress((void**)&h,     g_h);
    cudaGetSymbolAddress((void**)&qkT,   g_qkT);
    cudaGetSymbolAddress((void**)&v2,    g_v2);
    cudaGetSymbolAddress((void**)&attn,  g_attn);
    cudaGetSymbolAddress((void**)&attnh, g_attnh);
    cudaGetSymbolAddress((void**)&av2,   g_av2);
    cudaGetSymbolAddress((void**)&wqkT,  g_wqkT);
    cudaGetSymbolAddress((void**)&woutT, g_woutT);

    cudaFuncSetAttribute(hgemm, cudaFuncAttributeMaxDynamicSharedMemorySize, GSMEM);

    gn_stats<<<NB * 32, 256>>>(x);                        // 0
    gn_apply<<<(BT * NC) / 256, 256>>>(x, gn_scale, gn_bias); // 1
    tr_wqkv<<<192, 256>>>(w_qkv, wqkT);                   // 2

    // 3: GEMM 2a: qkT[feat 0..4095][bt]  (m=feat, n=bt) — profiler target
    hgemm<<<dim3(BT / 128, 4096 / 256, 1), 256, GSMEM>>>(
        wqkT, h, qkT, NC,
        512, 512, BT,
        1, 0, 0, 0, 0, 0, 0,
        1.0f, b_qkv, nullptr, nullptr, 1, 1);

    tr_wout<<<dim3(64, 16), 256>>>(w_out, woutT);         // 4

    // 5: GEMM 2b: v2[bt][f]  (m=bt, n=f; B = V-weight rows)
    hgemm<<<dim3(NF / 128, BT / 256, 1), 256, GSMEM>>>(
        h, wqkT + 4096LL * 512, v2, NC,
        512, 512, NF,
        1, 0, 0, 0, 0, 0, 0,
        1.0f, nullptr, b_qkv, nullptr, 1, 2);

    // 6: GEMM 3: logits[z][c][d] = (1/32) Q·K ; z=b*4+h, fp32 out
    hgemm<<<dim3(NC / 128, NC / 256, 32), 256, GSMEM>>>(
        qkT, qkT + 2048LL * BT, attn, NT,
        BT, BT, NC,
        NH,
        512LL * BT, NT, 512LL * BT, NT,
        (long long)NC * NC, 4LL * NC * NC,
        1.0f / 32.0f, nullptr, nullptr, nullptr, 0, 0);

    softmax512<<<32 * NC, 256>>>(attn, attnh);            // 7

    // 8: GEMM 5: av2[b*1024+t][h*512+c] = sum_d V[t,d]·P[c,d]  (m=t, n=c)
    hgemm<<<dim3(NC / 128, NT / 256, 32), 256, GSMEM>>>(
        v2, attnh, av2, NC,
        NF, NC, NF,
        NH,
        512, (long long)NT * NF,
        (long long)NC * NC, 4LL * NC * NC,
        512, (long long)NT * NF,
        1.0f, nullptr, nullptr, nullptr, 1, 0);

    // 9: GEMM 6: out[b][t][c] = av2 @ woutT^T + b_out + x  (m=t, n=c, fp32+resid)
    hgemm<<<dim3(NC / 128, NT / 256, NB), 256, GSMEM>>>(
        av2, woutT, out, NF,
        NF, NF, NC,
        1,
        0, (long long)NT * NF, 0, 0,
        0, (long long)NT * NC,
        1.0f, nullptr, b_out, x, 0, 0);
}

// round 7
// speedup vs baseline: 1.0044x; 1.0044x over previous
#include <cuda_runtime.h>
#include <cuda_fp16.h>
#include <cstdint>

#define NB 8
#define NT 1024
#define NC 512
#define NH 4
#define BT (NB*NT)          // 8192
#define NF 2048             // NH*NC

// ---------------- scratch (device globals) ----------------
__device__ __half g_h[BT * NC];                     // [bt][c]
__device__ __half g_qkT[(long long)4096 * BT];      // rows 0..2047 Q(h*512+c), 2048..4095 K ; [row][bt]
__device__ __half g_v2[(long long)BT * NF];         // [bt][h*512+d]
__device__ float  g_attn[32 * NC * NC];             // [b*4+h][c][d]  (fp32 logits)
__device__ __half g_attnh[32 * NC * NC];            // softmaxed, fp16
__device__ __half g_av2[(long long)BT * NF];        // [bt][h*512+c]
__device__ __half g_wqkT[6144 * NC];                // [row][c] row: sec*2048 + h*512 + c (sec 2 = V)
__device__ __half g_woutT[NC * NF];                 // [c][f]
__device__ float  g_mean[NB * 32];
__device__ float  g_rstd[NB * 32];

__device__ __forceinline__ uint32_t smem_u32(const void* p) {
    uint32_t a;
    asm("{ .reg .u64 t; cvta.to.shared.u64 t, %1; cvt.u32.u64 %0, t; }" : "=r"(a) : "l"(p));
    return a;
}
#define SWZ(o) ((o) ^ (((o) >> 3) & 0x70))

#define CPASYNC16(dst, src) \
    asm volatile("cp.async.cg.shared.global [%0], [%1], 16;" :: "r"(dst), "l"(src))
#define CP_COMMIT() asm volatile("cp.async.commit_group;" ::: "memory")
#define CP_WAIT2()  asm volatile("cp.async.wait_group 2;" ::: "memory")

#define LDSM4(r0, r1, r2, r3, addr) \
    asm volatile("ldmatrix.sync.aligned.m8n8.x4.shared.b16 {%0,%1,%2,%3}, [%4];" \
        : "=r"(r0), "=r"(r1), "=r"(r2), "=r"(r3) : "r"(addr))

#define HMMA16(d, a0, a1, a2, a3, b0, b1) \
    asm volatile("mma.sync.aligned.m16n8k16.row.col.f32.f16.f16.f32 " \
        "{%0,%1,%2,%3}, {%4,%5,%6,%7}, {%8,%9}, {%0,%1,%2,%3};" \
        : "+f"((d)[0]), "+f"((d)[1]), "+f"((d)[2]), "+f"((d)[3]) \
        : "r"(a0), "r"(a1), "r"(a2), "r"(a3), "r"(b0), "r"(b1))

// ---------------- GroupNorm ----------------
__global__ void gn_stats(const float* __restrict__ x) {
    int bg = blockIdx.x;
    int b = bg >> 5, g = bg & 31;
    const float* base = x + (size_t)b * (NT * NC) + g * 16;
    float s = 0.f, ss = 0.f;
    for (int idx = threadIdx.x; idx < NT * 16; idx += 256) {
        float v = base[(idx >> 4) * NC + (idx & 15)];
        s += v; ss += v * v;
    }
    for (int o = 16; o; o >>= 1) {
        s  += __shfl_xor_sync(0xffffffffu, s,  o);
        ss += __shfl_xor_sync(0xffffffffu, ss, o);
    }
    __shared__ float sa[8], sb[8];
    int wid = threadIdx.x >> 5;
    if ((threadIdx.x & 31) == 0) { sa[wid] = s; sb[wid] = ss; }
    __syncthreads();
    if (threadIdx.x == 0) {
        float S = 0.f, SS = 0.f;
        #pragma unroll
        for (int i = 0; i < 8; i++) { S += sa[i]; SS += sb[i]; }
        float inv = 1.0f / (NT * 16);
        float mean = S * inv;
        float var  = SS * inv - mean * mean;
        g_mean[bg] = mean;
        g_rstd[bg] = rsqrtf(var + 1e-5f);
    }
}

__global__ void gn_apply(const float* __restrict__ x,
                         const float* __restrict__ scale,
                         const float* __restrict__ bias) {
    int idx = blockIdx.x * 256 + threadIdx.x;
    if (idx >= BT * NC) return;
    int c = idx & (NC - 1);
    int b = idx >> 19;
    int bg = b * 32 + (c >> 4);
    float v = (x[idx] - g_mean[bg]) * g_rstd[bg] * scale[c] + bias[c];
    g_h[idx] = __float2half(v);
}

// ---------------- weight transposes ----------------
__global__ void tr_wqkv(const float* __restrict__ w, __half* __restrict__ wT) {
    __shared__ float t[32][33];
    int blk = blockIdx.x;             // 0..191
    int sec = blk >> 6;
    int within = blk & 63;
    int h = within >> 4, ct = within & 15;
    int c0 = ct * 32;
    int fbase = h * 1536 + sec;
    int r0 = sec * 2048 + h * 512 + c0;
    int tx = threadIdx.x & 31, ty = threadIdx.x >> 5;
    for (int k0 = 0; k0 < 512; k0 += 32) {
        #pragma unroll
        for (int j = 0; j < 4; j++) {
            int k = ty + j * 8;
            t[k][tx] = w[(long long)(k0 + k) * 6144 + fbase + 3 * (c0 + tx)];
        }
        __syncthreads();
        #pragma unroll
        for (int j = 0; j < 4; j++) {
            int cc = ty + j * 8;
            wT[(long long)(r0 + cc) * 512 + k0 + tx] = __float2half(t[tx][cc]);
        }
        __syncthreads();
    }
}

__global__ void tr_wout(const float* __restrict__ w, __half* __restrict__ wT) {
    __shared__ float t[32][33];
    int f0 = blockIdx.x * 32, c0 = blockIdx.y * 32;
    int tx = threadIdx.x & 31, ty = threadIdx.x >> 5;
    #pragma unroll
    for (int j = 0; j < 4; j++)
        t[ty + j * 8][tx] = w[(long long)(f0 + ty + j * 8) * 512 + c0 + tx];
    __syncthreads();
    #pragma unroll
    for (int j = 0; j < 4; j++)
        wT[(long long)(c0 + ty + j * 8) * 2048 + f0 + tx] = __float2half(t[tx][ty + j * 8]);
}

// ---------------- softmax: fp32 in, fp16 out ----------------
__global__ void softmax512(const float* __restrict__ a, __half* __restrict__ o) {
    const float* row = a + (size_t)blockIdx.x * NC;
    __half* orow = o + (size_t)blockIdx.x * NC;
    int tid = threadIdx.x;
    float v0 = row[tid], v1 = row[tid + 256];
    float m = fmaxf(v0, v1);
    __shared__ float red[8];
    for (int off = 16; off; off >>= 1) m = fmaxf(m, __shfl_xor_sync(0xffffffffu, m, off));
    if ((tid & 31) == 0) red[tid >> 5] = m;
    __syncthreads();
    m = red[0];
    #pragma unroll
    for (int i = 1; i < 8; i++) m = fmaxf(m, red[i]);
    __syncthreads();
    float e0 = __expf(v0 - m), e1 = __expf(v1 - m);
    float s = e0 + e1;
    for (int off = 16; off; off >>= 1) s += __shfl_xor_sync(0xffffffffu, s, off);
    if ((tid & 31) == 0) red[tid >> 5] = s;
    __syncthreads();
    s = 0.f;
    #pragma unroll
    for (int i = 0; i < 8; i++) s += red[i];
    float inv = 1.0f / s;
    orow[tid] = __float2half(e0 * inv);
    orow[tid + 256] = __float2half(e1 * inv);
}

// ---------------- fp16 mma.sync GEMM: CTA 256x128, warp 64x64, BK=64 ----------
// 4-stage cp.async pipeline, wait_group 2: compute of stage kb only requires
// stage kb resident; each stage's load hides behind a full block of compute.
// smem stage = A(256x64h=32KB)+B(128x64h=16KB)=48KB, 4 stages = 192KB.

#define STAGEB 49152
#define NSTAGE 4
#define GSMEM (NSTAGE * STAGEB)

__device__ __forceinline__ int qkv_map_m(int r) {
    int sec = r >> 11, rem = r & 2047;
    return (rem >> 9) * 1536 + 3 * (rem & 511) + sec;
}
__device__ __forceinline__ int qkv_map_v(int n) {
    return (n >> 9) * 1536 + 3 * (n & 511) + 2;
}

__global__ void __launch_bounds__(256, 1)
hgemm(const __half* __restrict__ A, const __half* __restrict__ B, void* __restrict__ Cv,
      int K, long long Asm, long long Bsn, long long Csm,
      int zInner, long long Abi, long long Abo, long long Bbi, long long Bbo,
      long long Cbi, long long Cbo, float alpha,
      const float* __restrict__ bias_m, const float* __restrict__ bias_n,
      const float* __restrict__ resid, int c16, int bmode) {
    extern __shared__ char smem[];
    uint32_t sbase = smem_u32(smem);
    int tid = threadIdx.x, lane = tid & 31, wid = tid >> 5;
    int g = lane >> 2, qid = lane & 3;
    int wm = (wid & 3) * 64, wn = (wid >> 2) * 64;

    int z = blockIdx.z;
    int zi = z % zInner, zo = z / zInner;
    A += zi * Abi + zo * Abo;
    B += zi * Bbi + zo * Bbo;
    long long cbase = zi * Cbi + zo * Cbo;
    int m0 = blockIdx.y * 256;
    int n0 = blockIdx.x * 128;
    A += (long long)m0 * Asm;
    B += (long long)n0 * Bsn;

    // cp.async mapping: A 32KB = 2048 chunks (8/thread), B 16KB = 1024 chunks (4/thread)
    int row0 = tid >> 3, q0 = tid & 7;
    const __half* srcA = A + (long long)row0 * Asm + q0 * 8;
    const __half* srcB = B + (long long)row0 * Bsn + q0 * 8;
    uint32_t dstA = sbase + SWZ((uint32_t)(row0 * 128 + q0 * 16));
    uint32_t dstB = dstA + 32768;

    float acc[4][8][4];
    #pragma unroll
    for (int i = 0; i < 4; i++)
        #pragma unroll
        for (int j = 0; j < 8; j++)
            #pragma unroll
            for (int qq = 0; qq < 4; qq++) acc[i][j][qq] = 0.f;

    int KB = K >> 6;

    // prologue: fill 3 of 4 stages
    #pragma unroll
    for (int s = 0; s < 3; s++) {
        uint32_t so = s * STAGEB;
        #pragma unroll
        for (int t = 0; t < 8; t++)
            CPASYNC16(dstA + so + t * 4096, srcA + s * 64 + (long long)(32 * t) * Asm);
        #pragma unroll
        for (int t = 0; t < 4; t++)
            CPASYNC16(dstB + so + t * 4096, srcB + s * 64 + (long long)(32 * t) * Bsn);
        CP_COMMIT();
    }

    uint32_t baseA = (uint32_t)((wm + (lane & 15)) * 128 + (lane >> 4) * 16);
    uint32_t baseB = (uint32_t)((wn + (lane & 7) + ((lane >> 4) & 1) * 8) * 128 + ((lane >> 3) & 1) * 16);

    int st = 0;
    for (int kb = 0; kb < KB; kb++) {
        CP_WAIT2();
        __syncthreads();
        // issue stage kb+3
        if (kb + 3 < KB) {
            int s3 = st + 3; if (s3 >= NSTAGE) s3 -= NSTAGE;
            uint32_t so = (uint32_t)s3 * STAGEB;
            #pragma unroll
            for (int t = 0; t < 8; t++)
                CPASYNC16(dstA + so + t * 4096, srcA + (kb + 3) * 64 + (long long)(32 * t) * Asm);
            #pragma unroll
            for (int t = 0; t < 4; t++)
                CPASYNC16(dstB + so + t * 4096, srcB + (kb + 3) * 64 + (long long)(32 * t) * Bsn);
        }
        CP_COMMIT();

        uint32_t sA = sbase + st * STAGEB;
        uint32_t sB = sA + 32768;

        #pragma unroll
        for (int ks = 0; ks < 4; ks++) {
            uint32_t a[4][4], bf[4][4];
            #pragma unroll
            for (int mt = 0; mt < 4; mt++)
                LDSM4(a[mt][0], a[mt][1], a[mt][2], a[mt][3],
                      sA + SWZ(baseA + mt * 2048 + ks * 32));
            #pragma unroll
            for (int ntp = 0; ntp < 4; ntp++)
                LDSM4(bf[ntp][0], bf[ntp][1], bf[ntp][2], bf[ntp][3],
                      sB + SWZ(baseB + ntp * 2048 + ks * 32));
            #pragma unroll
            for (int mt = 0; mt < 4; mt++)
                #pragma unroll
                for (int nt = 0; nt < 8; nt++) {
                    uint32_t b0 = bf[nt >> 1][(nt & 1) * 2];
                    uint32_t b1 = bf[nt >> 1][(nt & 1) * 2 + 1];
                    HMMA16(acc[mt][nt], a[mt][0], a[mt][1], a[mt][2], a[mt][3], b0, b1);
                }
        }
        st++; if (st == NSTAGE) st = 0;
    }

    // ---------------- epilogue ----------------
    #pragma unroll
    for (int mt = 0; mt < 4; mt++) {
        int r = m0 + wm + 16 * mt + g;
        float bm0 = 0.f, bm1 = 0.f;
        if (bias_m) {
            if (bmode == 1) { bm0 = bias_m[qkv_map_m(r)]; bm1 = bias_m[qkv_map_m(r + 8)]; }
            else            { bm0 = bias_m[r]; bm1 = bias_m[r + 8]; }
        }
        #pragma unroll
        for (int nt = 0; nt < 8; nt++) {
            float* c = acc[mt][nt];
            int n = n0 + wn + 8 * nt + qid * 2;
            float bn0 = 0.f, bn1 = 0.f;
            if (bias_n) {
                if (bmode == 2) { bn0 = bias_n[qkv_map_v(n)]; bn1 = bias_n[qkv_map_v(n + 1)]; }
                else            { bn0 = bias_n[n]; bn1 = bias_n[n + 1]; }
            }
            float v00 = c[0] * alpha + bm0 + bn0;
            float v01 = c[1] * alpha + bm0 + bn1;
            float v10 = c[2] * alpha + bm1 + bn0;
            float v11 = c[3] * alpha + bm1 + bn1;
            long long o0 = cbase + (long long)r * Csm + n;
            long long o1 = cbase + (long long)(r + 8) * Csm + n;
            if (c16) {
                *(__half2*)((__half*)Cv + o0) = __floats2half2_rn(v00, v01);
                *(__half2*)((__half*)Cv + o1) = __floats2half2_rn(v10, v11);
            } else {
                float* C = (float*)Cv;
                if (resid) {
                    v00 += resid[o0]; v01 += resid[o0 + 1];
                    v10 += resid[o1]; v11 += resid[o1 + 1];
                }
                *(float2*)(C + o0) = make_float2(v00, v01);
                *(float2*)(C + o1) = make_float2(v10, v11);
            }
        }
    }
}

extern "C" void kernel_launch(void* const* d_in, const int* in_sizes, int n_in,
                              void* d_out, int out_size) {
    const float* x        = (const float*)d_in[0];
    const float* gn_scale = (const float*)d_in[1];
    const float* gn_bias  = (const float*)d_in[2];
    const float* w_qkv    = (const float*)d_in[3];
    const float* b_qkv    = (const float*)d_in[4];
    const float* w_out    = (const float*)d_in[5];
    const float* b_out    = (const float*)d_in[6];
    float* out = (float*)d_out;

    __half *h, *qkT, *v2, *attnh, *av2, *wqkT, *woutT;
    float *attn;
    cudaGetSymbolAddress((void**)&h,     g_h);
    cudaGetSymbolAddress((void**)&qkT,   g_qkT);
    cudaGetSymbolAddress((void**)&v2,    g_v2);
    cudaGetSymbolAddress((void**)&attn,  g_attn);
    cudaGetSymbolAddress((void**)&attnh, g_attnh);
    cudaGetSymbolAddress((void**)&av2,   g_av2);
    cudaGetSymbolAddress((void**)&wqkT,  g_wqkT);
    cudaGetSymbolAddress((void**)&woutT, g_woutT);

    cudaFuncSetAttribute(hgemm, cudaFuncAttributeMaxDynamicSharedMemorySize, GSMEM);

    gn_stats<<<NB * 32, 256>>>(x);                        // 0
    gn_apply<<<(BT * NC) / 256, 256>>>(x, gn_scale, gn_bias); // 1
    tr_wqkv<<<192, 256>>>(w_qkv, wqkT);                   // 2

    // 3: GEMM 2a: qkT[feat 0..4095][bt]  (m=feat, n=bt)
    hgemm<<<dim3(BT / 128, 4096 / 256, 1), 256, GSMEM>>>(
        wqkT, h, qkT, NC,
        512, 512, BT,
        1, 0, 0, 0, 0, 0, 0,
        1.0f, b_qkv, nullptr, nullptr, 1, 1);

    tr_wout<<<dim3(64, 16), 256>>>(w_out, woutT);         // 4

    // 5: GEMM 2b: v2[bt][f]  (m=bt, n=f; B = V-weight rows) — profiler target (-s 5)
    hgemm<<<dim3(NF / 128, BT / 256, 1), 256, GSMEM>>>(
        h, wqkT + 4096LL * 512, v2, NC,
        512, 512, NF,
        1, 0, 0, 0, 0, 0, 0,
        1.0f, nullptr, b_qkv, nullptr, 1, 2);

    // 6: GEMM 3: logits[z][c][d] = (1/32) Q·K ; z=b*4+h, fp32 out
    hgemm<<<dim3(NC / 128, NC / 256, 32), 256, GSMEM>>>(
        qkT, qkT + 2048LL * BT, attn, NT,
        BT, BT, NC,
        NH,
        512LL * BT, NT, 512LL * BT, NT,
        (long long)NC * NC, 4LL * NC * NC,
        1.0f / 32.0f, nullptr, nullptr, nullptr, 0, 0);

    softmax512<<<32 * NC, 256>>>(attn, attnh);            // 7

    // 8: GEMM 5: av2[b*1024+t][h*512+c] = sum_d V[t,d]·P[c,d]  (m=t, n=c)
    hgemm<<<dim3(NC / 128, NT / 256, 32), 256, GSMEM>>>(
        v2, attnh, av2, NC,
        NF, NC, NF,
        NH,
        512, (long long)NT * NF,
        (long long)NC * NC, 4LL * NC * NC,
        512, (long long)NT * NF,
        1.0f, nullptr, nullptr, nullptr, 1, 0);

    // 9: GEMM 6: out[b][t][c] = av2 @ woutT^T + b_out + x  (m=t, n=c, fp32+resid)
    hgemm<<<dim3(NC / 128, NT / 256, NB), 256, GSMEM>>>(
        av2, woutT, out, NF,
        NF, NF, NC,
        1,
        0, (long long)NT * NF, 0, 0,
        0, (long long)NT * NC,
        1.0f, nullptr, b_out, x, 0, 0);
}